// round 3
// baseline (speedup 1.0000x reference)
#include <cuda_runtime.h>
#include <cstdint>

#define B_   4
#define K_   200
#define DIM_ 256
#define TT   8   // frames per block (one warp per frame)

// ---------------- device scratch (no allocations allowed) ----------------
__device__ float g_left [B_ * K_ * 8];
__device__ float g_right[B_ * K_ * 8];
__device__ float g_ts[B_ * K_];
__device__ float g_te[B_ * K_];

__device__ __forceinline__ float silu_f(float x) {
    // x * sigmoid(x) = x / (1 + exp(-x)); saturates correctly at +-inf exp
    return __fdividef(x, 1.0f + __expf(-x));
}

// ---------------- kernel 0: token boundary cumsum ----------------
__global__ void cumsum_kernel(const float* __restrict__ dur) {
    int b = threadIdx.x;
    if (b >= B_) return;
    float run = 0.0f;
    for (int k = 0; k < K_; k++) {
        float d = dur[b * K_ + k];
        g_ts[b * K_ + k] = run;
        run += d;
        g_te[b * K_ + k] = run;
    }
}

// ---------------- kernel 1: conv1d(k=3,'SAME') + SiLU for both branches ----------------
// One block per (b,k); 256 threads = input channels; 16 outputs (8 left + 8 right)
__global__ __launch_bounds__(256) void conv_kernel(
    const float* __restrict__ feat,
    const float* __restrict__ w1, const float* __restrict__ b1,
    const float* __restrict__ w2, const float* __restrict__ b2)
{
    int bk = blockIdx.x;
    int b = bk / K_, k = bk % K_;
    int i = threadIdx.x;

    const float* fb = feat + ((size_t)b * K_) * DIM_ + i;
    float fm = (k > 0)      ? fb[(k - 1) * DIM_] : 0.0f;
    float f0 =                fb[k * DIM_];
    float fp = (k + 1 < K_) ? fb[(k + 1) * DIM_] : 0.0f;

    float v[16];
    #pragma unroll
    for (int c = 0; c < 16; c++) v[c] = 0.0f;

    #pragma unroll
    for (int w = 0; w < 3; w++) {
        float x = (w == 0) ? fm : (w == 1) ? f0 : fp;
        const float* pw1 = w1 + ((size_t)w * DIM_ + i) * 8;
        const float* pw2 = w2 + ((size_t)w * DIM_ + i) * 8;
        #pragma unroll
        for (int c = 0; c < 8; c++) v[c]     = fmaf(x, pw1[c], v[c]);
        #pragma unroll
        for (int c = 0; c < 8; c++) v[8 + c] = fmaf(x, pw2[c], v[8 + c]);
    }

    // intra-warp tree reduce (16 values)
    #pragma unroll
    for (int c = 0; c < 16; c++) {
        #pragma unroll
        for (int off = 16; off > 0; off >>= 1)
            v[c] += __shfl_xor_sync(0xFFFFFFFFu, v[c], off);
    }

    __shared__ float red[8][16];
    int warp = threadIdx.x >> 5, lane = threadIdx.x & 31;
    if (lane == 0) {
        #pragma unroll
        for (int c = 0; c < 16; c++) red[warp][c] = v[c];
    }
    __syncthreads();

    if (threadIdx.x < 16) {
        int c = threadIdx.x;
        float s = 0.0f;
        #pragma unroll
        for (int w = 0; w < 8; w++) s += red[w][c];
        if (c < 8) {
            s += b1[c];
            g_left [(b * K_ + k) * 8 + c]       = silu_f(s);
        } else {
            s += b2[c - 8];
            g_right[(b * K_ + k) * 8 + (c - 8)] = silu_f(s);
        }
    }
}

// ---------------- kernel 2: fused logits/softmax/C/A/O/epilogue ----------------
// grid = (T/TT, B); 256 threads = 8 warps; warp w handles frame tBase+w
__global__ __launch_bounds__(256) void main_kernel(
    const float* __restrict__ feat,
    const float* __restrict__ sw1_w1, const float* __restrict__ sw1_b1,
    const float* __restrict__ sw1_w2, const float* __restrict__ sw1_b2,
    const float* __restrict__ sw2_w1, const float* __restrict__ sw2_b1,
    const float* __restrict__ sw2_w2, const float* __restrict__ sw2_b2,
    const float* __restrict__ p1_w,  const float* __restrict__ p1_b,
    const float* __restrict__ p2_w,  const float* __restrict__ p2_b,
    float* __restrict__ out, int T)
{
    // padded rows (17, 3) kill the 16-way / 2-way bank conflicts of [k][16]/[k][2]
    __shared__ float s_base1[K_][17];
    __shared__ float s_base2[K_][3];
    __shared__ float s_S[K_], s_E[K_];
    __shared__ __align__(16) float s_W[TT][K_];
    __shared__ float s_A[TT][16];
    __shared__ float s_w2t[16][16];   // transposed sw1_w2: [out j][in i]
    __shared__ float s_b2[16];

    int b = blockIdx.y;
    int tBase = blockIdx.x * TT;
    int tid = threadIdx.x;
    int warp = tid >> 5, lane = tid & 31;

    // ---- staging ----
    if (tid < K_) { s_S[tid] = g_ts[b * K_ + tid]; s_E[tid] = g_te[b * K_ + tid]; }
    { int i = tid >> 4, j = tid & 15; s_w2t[j][i] = sw1_w2[i * 16 + j]; }
    if (tid < 16) s_b2[tid] = sw1_b2[tid];

    // base1[k][j] = left[k] @ sw1_w1[2:10, j] + b1[j]  (t-independent part of layer 1)
    for (int idx = tid; idx < K_ * 16; idx += 256) {
        int k = idx >> 4, j = idx & 15;
        float s = sw1_b1[j];
        const float* lp = g_left + (b * K_ + k) * 8;
        #pragma unroll
        for (int c = 0; c < 8; c++) s = fmaf(lp[c], sw1_w1[(2 + c) * 16 + j], s);
        s_base1[k][j] = s;
    }
    // base2[k][j] = right[k] @ sw2_w1[2:10, j] + b1[j]
    for (int idx = tid; idx < K_ * 2; idx += 256) {
        int k = idx >> 1, j = idx & 1;
        float s = sw2_b1[j];
        const float* rp = g_right + (b * K_ + k) * 8;
        #pragma unroll
        for (int c = 0; c < 8; c++) s = fmaf(rp[c], sw2_w1[(2 + c) * 2 + j], s);
        s_base2[k][j] = s;
    }

    // S/E weight rows of sw1_w1 stay in registers for phase 2
    float u1[16], v1[16];
    #pragma unroll
    for (int j = 0; j < 16; j++) { u1[j] = sw1_w1[j]; v1[j] = sw1_w1[16 + j]; }

    __syncthreads();

    int t = tBase + warp;
    float tf = (float)t;
    bool valid = (t < T);           // warp-uniform

    // ---- phase 1: logits (cheap path) + softmax into s_W[warp][*] ----
    if (valid) {
        float u2a = sw2_w1[0], u2b = sw2_w1[1];
        float v2a = sw2_w1[2], v2b = sw2_w1[3];
        float w00 = sw2_w2[0], w01 = sw2_w2[1], w10 = sw2_w2[2], w11 = sw2_w2[3];
        float bb0 = sw2_b2[0], bb1 = sw2_b2[1];
        float pa = p1_w[0], pb = p1_w[1], pc = p1_b[0];

        float lmax = -1e30f;
        for (int k = lane; k < K_; k += 32) {
            float S = tf - s_S[k], E = s_E[k] - tf;
            float x0 = fmaf(S, u2a, fmaf(E, v2a, s_base2[k][0]));
            float x1 = fmaf(S, u2b, fmaf(E, v2b, s_base2[k][1]));
            float h0 = silu_f(x0), h1 = silu_f(x1);
            float y0 = silu_f(fmaf(h0, w00, fmaf(h1, w10, bb0)));
            float y1 = silu_f(fmaf(h0, w01, fmaf(h1, w11, bb1)));
            float lg = fmaf(y0, pa, fmaf(y1, pb, pc));
            s_W[warp][k] = lg;
            lmax = fmaxf(lmax, lg);
        }
        #pragma unroll
        for (int off = 16; off > 0; off >>= 1)
            lmax = fmaxf(lmax, __shfl_xor_sync(0xFFFFFFFFu, lmax, off));

        float lsum = 0.0f;
        for (int k = lane; k < K_; k += 32) {
            float e = __expf(s_W[warp][k] - lmax);
            s_W[warp][k] = e;
            lsum += e;
        }
        #pragma unroll
        for (int off = 16; off > 0; off >>= 1)
            lsum += __shfl_xor_sync(0xFFFFFFFFu, lsum, off);
        float inv = __frcp_rn(lsum);
        for (int k = lane; k < K_; k += 32) s_W[warp][k] *= inv;
    } else {
        for (int k = lane; k < K_; k += 32) s_W[warp][k] = 0.0f;
    }

    // ---- phase 2: C = 2-layer swish (expensive path), A = sum_k W_k * C_k ----
    {
        float A[16];
        #pragma unroll
        for (int j = 0; j < 16; j++) A[j] = 0.0f;

        if (valid) {
            for (int k = lane; k < K_; k += 32) {
                float S = tf - s_S[k], E = s_E[k] - tf;
                float wgt = s_W[warp][k];
                float h[16];
                #pragma unroll
                for (int j = 0; j < 16; j++)
                    h[j] = silu_f(fmaf(S, u1[j], fmaf(E, v1[j], s_base1[k][j])));
                #pragma unroll
                for (int j = 0; j < 16; j++) {
                    float z = s_b2[j];
                    #pragma unroll
                    for (int i = 0; i < 16; i++) z = fmaf(h[i], s_w2t[j][i], z);
                    A[j] = fmaf(wgt, silu_f(z), A[j]);
                }
            }
        }
        #pragma unroll
        for (int j = 0; j < 16; j++) {
            #pragma unroll
            for (int off = 16; off > 0; off >>= 1)
                A[j] += __shfl_xor_sync(0xFFFFFFFFu, A[j], off);
        }
        if (lane == 0) {
            #pragma unroll
            for (int j = 0; j < 16; j++) s_A[warp][j] = A[j];
        }
    }
    __syncthreads();

    // ---- phase 3: O[t][d] = sum_k W[t][k] * features[b][k][d], + A@p2 + bias ----
    {
        int d = tid;  // 256 threads cover DIM
        float acc[TT];
        #pragma unroll
        for (int tt = 0; tt < TT; tt++) acc[tt] = 0.0f;

        const float* fb = feat + ((size_t)b * K_) * DIM_ + d;
        for (int k = 0; k < K_; k += 4) {
            float f0 = fb[(k + 0) * DIM_];
            float f1 = fb[(k + 1) * DIM_];
            float f2 = fb[(k + 2) * DIM_];
            float f3 = fb[(k + 3) * DIM_];
            #pragma unroll
            for (int tt = 0; tt < TT; tt++) {
                float4 w4 = *(const float4*)&s_W[tt][k];  // broadcast LDS.128
                acc[tt] = fmaf(w4.x, f0, fmaf(w4.y, f1, fmaf(w4.z, f2, fmaf(w4.w, f3, acc[tt]))));
            }
        }

        float pw[16];
        #pragma unroll
        for (int p = 0; p < 16; p++) pw[p] = p2_w[p * DIM_ + d];
        float pbv = p2_b[d];

        float* ob = out + ((size_t)b * T + tBase) * DIM_ + d;
        #pragma unroll
        for (int tt = 0; tt < TT; tt++) {
            if (tBase + tt < T) {
                float o = acc[tt] + pbv;
                #pragma unroll
                for (int p = 0; p < 16; p++) o = fmaf(s_A[tt][p], pw[p], o);
                ob[tt * DIM_] = o;
            }
        }
    }
}

// ---------------- launcher ----------------
extern "C" void kernel_launch(void* const* d_in, const int* in_sizes, int n_in,
                              void* d_out, int out_size) {
    // metadata order: T, durations, features, conv1_w, conv1_b, conv2_w, conv2_b,
    // sw1_w1, sw1_b1, sw1_w2, sw1_b2, sw2_w1, sw2_b1, sw2_w2, sw2_b2,
    // p1_w, p1_b, p2_w, p2_b
    const float* durations = (const float*)d_in[1];
    const float* features  = (const float*)d_in[2];
    const float* conv1_w   = (const float*)d_in[3];
    const float* conv1_b   = (const float*)d_in[4];
    const float* conv2_w   = (const float*)d_in[5];
    const float* conv2_b   = (const float*)d_in[6];
    const float* sw1_w1    = (const float*)d_in[7];
    const float* sw1_b1    = (const float*)d_in[8];
    const float* sw1_w2    = (const float*)d_in[9];
    const float* sw1_b2    = (const float*)d_in[10];
    const float* sw2_w1    = (const float*)d_in[11];
    const float* sw2_b1    = (const float*)d_in[12];
    const float* sw2_w2    = (const float*)d_in[13];
    const float* sw2_b2    = (const float*)d_in[14];
    const float* p1_w      = (const float*)d_in[15];
    const float* p1_b      = (const float*)d_in[16];
    const float* p2_w      = (const float*)d_in[17];
    const float* p2_b      = (const float*)d_in[18];

    int T = out_size / (B_ * DIM_);

    cumsum_kernel<<<1, B_>>>(durations);
    conv_kernel<<<B_ * K_, 256>>>(features, conv1_w, conv1_b, conv2_w, conv2_b);

    dim3 grid((T + TT - 1) / TT, B_);
    main_kernel<<<grid, 256>>>(features,
                               sw1_w1, sw1_b1, sw1_w2, sw1_b2,
                               sw2_w1, sw2_b1, sw2_w2, sw2_b2,
                               p1_w, p1_b, p2_w, p2_b,
                               (float*)d_out, T);
}